// round 4
// baseline (speedup 1.0000x reference)
#include <cuda_runtime.h>
#include <math.h>

#define NN 100000
#define EE 1600000
#define HH 128
#define CC 40

// Scratch (device globals — allocation-free per harness rules)
__device__ float g_xr[(size_t)NN * HH];   // rel-transformed features (scatter source)
__device__ float g_z1[(size_t)NN * HH];   // layer1 accumulator: x@W_root1 + b1 (+ scatter)
__device__ float g_z2[(size_t)NN * HH];   // layer2 accumulator
__device__ float g_x1[(size_t)NN * HH];   // relu(z1) saved for final concat

// ---------------------------------------------------------------------------
// Dual GEMM: grid.y==0 computes A@W_rel -> g_xr ; grid.y==1 computes
// A@W_root + bias -> z buffer. LAYER==2 applies relu to A on load and saves
// relu(A) to g_x1 (from the grid.y==0 blocks only).
// Tile: 128(M) x 128(N) x 128(K, single shot), 256 threads, 8x8 microtile.
// ---------------------------------------------------------------------------
template <int LAYER>
__global__ __launch_bounds__(256, 1) void gemm_dual(
    const float* __restrict__ Ain,
    const float* __restrict__ Wrel,
    const float* __restrict__ Wroot,
    const float* __restrict__ bias)
{
    extern __shared__ float sm[];
    float* As = sm;                 // 128 rows x 132 stride (padded)
    float* Bs = sm + 128 * 132;     // 128 x 128, [k][n]

    const float* A    = (LAYER == 1) ? Ain : g_z1;
    float*       outz = (LAYER == 1) ? g_z1 : g_z2;

    const int tid   = threadIdx.x;
    const int m0    = blockIdx.x * 128;
    const int which = blockIdx.y;      // 0 = rel path, 1 = root path
    const float* W  = which ? Wroot : Wrel;

    // Load A tile (with optional relu + save) and B tile
    #pragma unroll
    for (int i = 0; i < 16; i++) {
        int f   = tid + i * 256;       // 0..4095 float4 slots
        int row = f >> 5;              // 0..127
        int k4  = (f & 31) << 2;       // 0,4,...,124
        float4 v = make_float4(0.f, 0.f, 0.f, 0.f);
        int gm = m0 + row;
        if (gm < NN) v = *(const float4*)(A + (size_t)gm * HH + k4);
        if (LAYER == 2) {
            v.x = fmaxf(v.x, 0.f); v.y = fmaxf(v.y, 0.f);
            v.z = fmaxf(v.z, 0.f); v.w = fmaxf(v.w, 0.f);
            if (which == 0 && gm < NN)
                *(float4*)(g_x1 + (size_t)gm * HH + k4) = v;
        }
        *(float4*)(As + row * 132 + k4) = v;
        ((float4*)Bs)[f] = ((const float4*)W)[f];   // identical [k][n] layout
    }
    __syncthreads();

    const int tx = tid & 15, ty = tid >> 4;
    const int n8 = tx * 8,  m8 = ty * 8;

    float acc[8][8];
    #pragma unroll
    for (int i = 0; i < 8; i++)
        #pragma unroll
        for (int j = 0; j < 8; j++) acc[i][j] = 0.f;

    #pragma unroll 4
    for (int k = 0; k < 128; k++) {
        float a[8], b[8];
        #pragma unroll
        for (int i = 0; i < 8; i++) a[i] = As[(m8 + i) * 132 + k];
        float4 b0 = *(float4*)(Bs + k * 128 + n8);
        float4 b1 = *(float4*)(Bs + k * 128 + n8 + 4);
        b[0] = b0.x; b[1] = b0.y; b[2] = b0.z; b[3] = b0.w;
        b[4] = b1.x; b[5] = b1.y; b[6] = b1.z; b[7] = b1.w;
        #pragma unroll
        for (int i = 0; i < 8; i++)
            #pragma unroll
            for (int j = 0; j < 8; j++)
                acc[i][j] = fmaf(a[i], b[j], acc[i][j]);
    }

    float bv[8];
    #pragma unroll
    for (int j = 0; j < 8; j++) bv[j] = which ? bias[n8 + j] : 0.f;

    float* outp = which ? outz : g_xr;
    #pragma unroll
    for (int i = 0; i < 8; i++) {
        int gm = m0 + m8 + i;
        if (gm < NN) {
            float* o = outp + (size_t)gm * HH + n8;
            float4 r0 = make_float4(acc[i][0] + bv[0], acc[i][1] + bv[1],
                                    acc[i][2] + bv[2], acc[i][3] + bv[3]);
            float4 r1 = make_float4(acc[i][4] + bv[4], acc[i][5] + bv[5],
                                    acc[i][6] + bv[6], acc[i][7] + bv[7]);
            *(float4*)o       = r0;
            *(float4*)(o + 4) = r1;
        }
    }
}

// ---------------------------------------------------------------------------
// Scatter-add: z[dst] += g_xr[src], one warp per edge, lane = float4 chunk.
// Vector red (sm_90+) quarters the atomic-lane count.
// ---------------------------------------------------------------------------
template <int LAYER>
__global__ __launch_bounds__(256) void scatter_add(const int* __restrict__ ei)
{
    float* z = (LAYER == 1) ? g_z1 : g_z2;
    int gw   = (blockIdx.x * blockDim.x + threadIdx.x) >> 5;
    int lane = threadIdx.x & 31;
    if (gw >= EE) return;
    int s = __ldg(ei + gw);
    int d = __ldg(ei + EE + gw);
    float4 v = *(const float4*)(g_xr + (size_t)s * HH + lane * 4);
    float* p = z + (size_t)d * HH + lane * 4;
    asm volatile("red.global.add.v4.f32 [%0], {%1, %2, %3, %4};"
                 :: "l"(p), "f"(v.x), "f"(v.y), "f"(v.z), "f"(v.w)
                 : "memory");
}

// ---------------------------------------------------------------------------
// Final: logits = [x1, relu(z2)] @ W_lin + b ; log_softmax. 64 nodes/block,
// 4 threads/node (10 classes each), quad-shuffle softmax reduction.
// ---------------------------------------------------------------------------
__global__ __launch_bounds__(256, 1) void final_kernel(
    const float* __restrict__ Wlin,   // [256][40]
    const float* __restrict__ blin,   // [40]
    float* __restrict__ out)          // [N][40]
{
    extern __shared__ float sm[];
    float* shH = sm;                   // 64 x 264 (padded)
    float* shW = sm + 64 * 264;        // 40 x 264 (W transposed: [c][k])
    float* shB = shW + 40 * 264;       // 40

    const int tid = threadIdx.x;
    const int n0  = blockIdx.x * 64;

    // W_lin transpose into smem
    #pragma unroll
    for (int i = 0; i < 40; i++) {
        int idx = tid + i * 256;       // 0..10239
        int c = idx >> 8, k = idx & 255;
        shW[c * 264 + k] = Wlin[k * CC + c];
    }
    if (tid < CC) shB[tid] = blin[tid];

    // h tile: cols 0..127 = x1, 128..255 = relu(z2)
    #pragma unroll
    for (int i = 0; i < 16; i++) {
        int f    = tid + i * 256;      // 0..4095 float4 slots
        int node = f >> 6;
        int part = f & 63;
        int gm   = n0 + node;
        float4 v = make_float4(0.f, 0.f, 0.f, 0.f);
        if (gm < NN) {
            if (part < 32) {
                v = *(const float4*)(g_x1 + (size_t)gm * HH + part * 4);
            } else {
                v = *(const float4*)(g_z2 + (size_t)gm * HH + (part - 32) * 4);
                v.x = fmaxf(v.x, 0.f); v.y = fmaxf(v.y, 0.f);
                v.z = fmaxf(v.z, 0.f); v.w = fmaxf(v.w, 0.f);
            }
        }
        *(float4*)(shH + node * 264 + part * 4) = v;
    }
    __syncthreads();

    const int node = tid >> 2, q = tid & 3, c0 = q * 10;
    float acc[10];
    #pragma unroll
    for (int j = 0; j < 10; j++) acc[j] = shB[c0 + j];

    for (int k4 = 0; k4 < 64; k4++) {
        float4 h = *(float4*)(shH + node * 264 + k4 * 4);
        #pragma unroll
        for (int j = 0; j < 10; j++) {
            float4 w = *(float4*)(shW + (c0 + j) * 264 + k4 * 4);
            acc[j] += h.x * w.x + h.y * w.y + h.z * w.z + h.w * w.w;
        }
    }

    // log_softmax over the node's 40 classes (held by a 4-thread quad)
    float m = acc[0];
    #pragma unroll
    for (int j = 1; j < 10; j++) m = fmaxf(m, acc[j]);
    m = fmaxf(m, __shfl_xor_sync(0xffffffffu, m, 1));
    m = fmaxf(m, __shfl_xor_sync(0xffffffffu, m, 2));
    float s = 0.f;
    #pragma unroll
    for (int j = 0; j < 10; j++) s += __expf(acc[j] - m);
    s += __shfl_xor_sync(0xffffffffu, s, 1);
    s += __shfl_xor_sync(0xffffffffu, s, 2);
    float lse = m + __logf(s);

    int gm = n0 + node;
    if (gm < NN) {
        #pragma unroll
        for (int j = 0; j < 10; j++)
            out[(size_t)gm * CC + c0 + j] = acc[j] - lse;
    }
}

extern "C" void kernel_launch(void* const* d_in, const int* in_sizes, int n_in,
                              void* d_out, int out_size)
{
    const float* x       = (const float*)d_in[0];
    const int*   ei      = (const int*)  d_in[1];
    const float* W_rel1  = (const float*)d_in[2];
    const float* b_rel1  = (const float*)d_in[3];
    const float* W_root1 = (const float*)d_in[4];
    const float* W_rel2  = (const float*)d_in[5];
    const float* b_rel2  = (const float*)d_in[6];
    const float* W_root2 = (const float*)d_in[7];
    const float* W_lin   = (const float*)d_in[8];
    const float* b_lin   = (const float*)d_in[9];
    float* out = (float*)d_out;

    const int GEMM_SMEM = (128 * 132 + 128 * 128) * 4;           // 133120 B
    const int FIN_SMEM  = (64 * 264 + 40 * 264 + 40) * 4;        // 109984 B
    cudaFuncSetAttribute(gemm_dual<1>, cudaFuncAttributeMaxDynamicSharedMemorySize, GEMM_SMEM);
    cudaFuncSetAttribute(gemm_dual<2>, cudaFuncAttributeMaxDynamicSharedMemorySize, GEMM_SMEM);
    cudaFuncSetAttribute(final_kernel, cudaFuncAttributeMaxDynamicSharedMemorySize, FIN_SMEM);

    dim3 ggrid((NN + 127) / 128, 2);             // 782 x 2
    const int SC_BLOCKS = EE / 8;                 // 8 edges (warps) per 256-thr block

    gemm_dual<1><<<ggrid, 256, GEMM_SMEM>>>(x, W_rel1, W_root1, b_rel1);
    scatter_add<1><<<SC_BLOCKS, 256>>>(ei);
    gemm_dual<2><<<ggrid, 256, GEMM_SMEM>>>(nullptr, W_rel2, W_root2, b_rel2);
    scatter_add<2><<<SC_BLOCKS, 256>>>(ei);
    final_kernel<<<(NN + 63) / 64, 256, FIN_SMEM>>>(W_lin, b_lin, out);
}